// round 4
// baseline (speedup 1.0000x reference)
#include <cuda_runtime.h>
#include <math_constants.h>

// ---------------- problem constants ----------------
#define N_NODES 100000
#define N_EDGES 1600000
#define DIM_IN  128
#define DIM_HID 128
#define DIM_OUT 64
#define NEG_SLOPE 0.2f

#define SCAN_BLK 1024
#define N_SCAN_BLOCKS ((N_NODES + SCAN_BLK - 1) / SCAN_BLK)   // 98

// ---------------- scratch (device globals; no allocation allowed) ----------
__device__ float g_h1[(size_t)N_NODES * DIM_HID];
__device__ float g_acc[(size_t)N_NODES * DIM_HID];
__device__ float g_h2[(size_t)N_NODES * DIM_OUT];
__device__ float g_asrc[N_NODES];
__device__ float g_adst[N_NODES];
__device__ float g_p[2 * 128];

// CSR scratch
__device__ int g_cnt[N_NODES];
__device__ int g_incl[N_NODES];
__device__ int g_bsum[N_SCAN_BLOCKS];
__device__ int g_boff[N_SCAN_BLOCKS];
__device__ int g_rowptr[N_NODES + 1];
__device__ int g_woff[N_NODES];
__device__ int g_csr_src[N_EDGES];

// ---------------- CSR build ----------------
__global__ void hist_kernel(const int* __restrict__ dst) {
    int e = blockIdx.x * blockDim.x + threadIdx.x;
    if (e >= N_EDGES) return;
    int d = dst[e];
    if ((unsigned)d < N_NODES) atomicAdd(&g_cnt[d], 1);
}

__global__ void scan1_kernel() {
    __shared__ int s[SCAN_BLK];
    int tid = threadIdx.x;
    int i = blockIdx.x * SCAN_BLK + tid;
    s[tid] = (i < N_NODES) ? g_cnt[i] : 0;
    __syncthreads();
    #pragma unroll
    for (int off = 1; off < SCAN_BLK; off <<= 1) {
        int v = (tid >= off) ? s[tid - off] : 0;
        __syncthreads();
        s[tid] += v;
        __syncthreads();
    }
    if (i < N_NODES) g_incl[i] = s[tid];
    if (tid == SCAN_BLK - 1) g_bsum[blockIdx.x] = s[tid];
}

__global__ void scan2_kernel() {
    __shared__ int s[128];
    int tid = threadIdx.x;
    int v0 = (tid < N_SCAN_BLOCKS) ? g_bsum[tid] : 0;
    s[tid] = v0;
    __syncthreads();
    #pragma unroll
    for (int off = 1; off < 128; off <<= 1) {
        int v = (tid >= off) ? s[tid - off] : 0;
        __syncthreads();
        s[tid] += v;
        __syncthreads();
    }
    if (tid < N_SCAN_BLOCKS) g_boff[tid] = s[tid] - v0;
}

__global__ void scan3_kernel() {
    int i = blockIdx.x * blockDim.x + threadIdx.x;
    if (i >= N_NODES) return;
    int excl = g_incl[i] - g_cnt[i] + g_boff[i / SCAN_BLK];
    g_rowptr[i] = excl;
    g_woff[i]   = excl;
    if (i == 0) g_rowptr[N_NODES] = N_EDGES;
}

__global__ void scatter_kernel(const int* __restrict__ src, const int* __restrict__ dst) {
    int e = blockIdx.x * blockDim.x + threadIdx.x;
    if (e >= N_EDGES) return;
    int s = src[e];
    int d = dst[e];
    if ((unsigned)s >= N_NODES || (unsigned)d >= N_NODES) return;
    int pos = atomicAdd(&g_woff[d], 1);
    g_csr_src[pos] = s;
}

// ---------------- per-layer node prep ----------------
__global__ void compute_p_kernel(const float* __restrict__ Ws, const float* __restrict__ as_,
                                 const float* __restrict__ Wd, const float* __restrict__ ad_,
                                 int C) {
    int i = threadIdx.x;  // 0..127
    float s = 0.f, d = 0.f;
    for (int c = 0; c < C; c++) {
        s += Ws[i * C + c] * as_[c];
        d += Wd[i * C + c] * ad_[c];
    }
    g_p[i] = s;
    g_p[128 + i] = d;
}

__global__ void node_av_kernel(const float* __restrict__ feat) {
    int warp = (blockIdx.x * blockDim.x + threadIdx.x) >> 5;
    int lane = threadIdx.x & 31;
    if (warp >= N_NODES) return;
    const float* f = feat + (size_t)warp * 128;
    float4 v = ((const float4*)f)[lane];
    float4 ps = ((const float4*)g_p)[lane];
    float4 pd = ((const float4*)(g_p + 128))[lane];
    float s = v.x * ps.x + v.y * ps.y + v.z * ps.z + v.w * ps.w;
    float d = v.x * pd.x + v.y * pd.y + v.z * pd.z + v.w * pd.w;
    #pragma unroll
    for (int o = 16; o > 0; o >>= 1) {
        s += __shfl_down_sync(0xffffffffu, s, o);
        d += __shfl_down_sync(0xffffffffu, d, o);
    }
    if (lane == 0) {
        g_asrc[warp] = s;
        g_adst[warp] = d;
    }
}

// ---------------- TF32 tensor-core GEMM (3xTF32) ----------------
__device__ __forceinline__ unsigned f2tf32(float x) {
    unsigned u;
    asm("cvt.rna.tf32.f32 %0, %1;" : "=r"(u) : "f"(x));
    return u;
}

__device__ __forceinline__ void mma_tf32(float c[4], const unsigned a[4], const unsigned b[2]) {
    asm volatile(
        "mma.sync.aligned.m16n8k8.row.col.f32.tf32.tf32.f32 "
        "{%0,%1,%2,%3}, {%4,%5,%6,%7}, {%8,%9}, {%0,%1,%2,%3};"
        : "+f"(c[0]), "+f"(c[1]), "+f"(c[2]), "+f"(c[3])
        : "r"(a[0]), "r"(a[1]), "r"(a[2]), "r"(a[3]), "r"(b[0]), "r"(b[1]));
}

// H[nrows, COUT] = X[nrows, 128] @ W[128, COUT];  COUT in {128, 64}
template<int COUT>
__global__ __launch_bounds__(256, 2)
void gemm_tf32_kernel(const float* __restrict__ X, const float* __restrict__ W,
                      float* __restrict__ H, int nrows) {
    constexpr int K = 128;
    constexpr int KTILE = 16;
    constexpr int NCHUNK = K / KTILE;      // 8
    constexpr int MBLK = 128;
    constexpr int MT = (COUT == 128) ? 2 : 1;   // 16-row m-tiles per warp
    constexpr int WM = MT * 16;                 // warp rows
    constexpr int XS = KTILE + 1;               // 17
    constexpr int WS = COUT + 1;

    __shared__ float Xh[MBLK * XS], Xl[MBLK * XS];
    __shared__ float Wh[KTILE * WS], Wl[KTILE * WS];

    int tid  = threadIdx.x;
    int wid  = tid >> 5;
    int lane = tid & 31;
    int gid  = lane >> 2;       // 0..7
    int tig  = lane & 3;        // 0..3
    int warp_m = (COUT == 128) ? (wid >> 1) : wid;
    int warp_n = (COUT == 128) ? (wid & 1) : 0;
    int row0 = blockIdx.x * MBLK;

    float c[MT][8][4];
    #pragma unroll
    for (int mt = 0; mt < MT; mt++)
        #pragma unroll
        for (int nt = 0; nt < 8; nt++)
            #pragma unroll
            for (int i = 0; i < 4; i++) c[mt][nt][i] = 0.0f;

    for (int ch = 0; ch < NCHUNK; ch++) {
        // --- load X chunk [MBLK x KTILE], split hi/lo ---
        #pragma unroll
        for (int t = 0; t < 2; t++) {
            int idx = tid + t * 256;            // 0..511 float4 slots
            int r  = idx >> 2;                  // row 0..127
            int c4 = (idx & 3) * 4;             // col 0,4,8,12
            float4 v = make_float4(0.f, 0.f, 0.f, 0.f);
            if (row0 + r < nrows)
                v = *(const float4*)&X[(size_t)(row0 + r) * K + ch * KTILE + c4];
            float hx = __uint_as_float(f2tf32(v.x));
            float hy = __uint_as_float(f2tf32(v.y));
            float hz = __uint_as_float(f2tf32(v.z));
            float hw = __uint_as_float(f2tf32(v.w));
            float* xh = &Xh[r * XS + c4];
            float* xl = &Xl[r * XS + c4];
            xh[0] = hx; xh[1] = hy; xh[2] = hz; xh[3] = hw;
            xl[0] = __uint_as_float(f2tf32(v.x - hx));
            xl[1] = __uint_as_float(f2tf32(v.y - hy));
            xl[2] = __uint_as_float(f2tf32(v.z - hz));
            xl[3] = __uint_as_float(f2tf32(v.w - hw));
        }
        // --- load W chunk [KTILE x COUT], split hi/lo ---
        #pragma unroll
        for (int t = 0; t < (KTILE * COUT / 4) / 256; t++) {
            int idx = tid + t * 256;
            int r  = idx / (COUT / 4);
            int c4 = (idx % (COUT / 4)) * 4;
            float4 v = *(const float4*)&W[(size_t)(ch * KTILE + r) * COUT + c4];
            float hx = __uint_as_float(f2tf32(v.x));
            float hy = __uint_as_float(f2tf32(v.y));
            float hz = __uint_as_float(f2tf32(v.z));
            float hw = __uint_as_float(f2tf32(v.w));
            float* wh = &Wh[r * WS + c4];
            float* wl = &Wl[r * WS + c4];
            wh[0] = hx; wh[1] = hy; wh[2] = hz; wh[3] = hw;
            wl[0] = __uint_as_float(f2tf32(v.x - hx));
            wl[1] = __uint_as_float(f2tf32(v.y - hy));
            wl[2] = __uint_as_float(f2tf32(v.z - hz));
            wl[3] = __uint_as_float(f2tf32(v.w - hw));
        }
        __syncthreads();

        #pragma unroll
        for (int ks = 0; ks < KTILE / 8; ks++) {
            int kb = ks * 8;
            // A fragments for this k-step (hi and lo)
            unsigned ah[MT][4], al[MT][4];
            #pragma unroll
            for (int mt = 0; mt < MT; mt++) {
                int rA = warp_m * WM + mt * 16;
                ah[mt][0] = __float_as_uint(Xh[(rA + gid) * XS + kb + tig]);
                ah[mt][1] = __float_as_uint(Xh[(rA + gid + 8) * XS + kb + tig]);
                ah[mt][2] = __float_as_uint(Xh[(rA + gid) * XS + kb + tig + 4]);
                ah[mt][3] = __float_as_uint(Xh[(rA + gid + 8) * XS + kb + tig + 4]);
                al[mt][0] = __float_as_uint(Xl[(rA + gid) * XS + kb + tig]);
                al[mt][1] = __float_as_uint(Xl[(rA + gid + 8) * XS + kb + tig]);
                al[mt][2] = __float_as_uint(Xl[(rA + gid) * XS + kb + tig + 4]);
                al[mt][3] = __float_as_uint(Xl[(rA + gid + 8) * XS + kb + tig + 4]);
            }
            #pragma unroll
            for (int nt = 0; nt < 8; nt++) {
                int col = warp_n * 64 + nt * 8 + gid;
                unsigned bh[2], bl[2];
                bh[0] = __float_as_uint(Wh[(kb + tig) * WS + col]);
                bh[1] = __float_as_uint(Wh[(kb + tig + 4) * WS + col]);
                bl[0] = __float_as_uint(Wl[(kb + tig) * WS + col]);
                bl[1] = __float_as_uint(Wl[(kb + tig + 4) * WS + col]);
                #pragma unroll
                for (int mt = 0; mt < MT; mt++) {
                    mma_tf32(c[mt][nt], ah[mt], bh);   // Ah*Bh
                    mma_tf32(c[mt][nt], al[mt], bh);   // Al*Bh
                    mma_tf32(c[mt][nt], ah[mt], bl);   // Ah*Bl
                }
            }
        }
        __syncthreads();
    }

    // epilogue
    #pragma unroll
    for (int mt = 0; mt < MT; mt++) {
        int r0 = row0 + warp_m * WM + mt * 16 + gid;
        #pragma unroll
        for (int nt = 0; nt < 8; nt++) {
            int col = warp_n * 64 + nt * 8 + 2 * tig;
            if (r0 < nrows) {
                float2 v0 = make_float2(c[mt][nt][0], c[mt][nt][1]);
                *(float2*)&H[(size_t)r0 * COUT + col] = v0;
            }
            if (r0 + 8 < nrows) {
                float2 v1 = make_float2(c[mt][nt][2], c[mt][nt][3]);
                *(float2*)&H[(size_t)(r0 + 8) * COUT + col] = v1;
            }
        }
    }
}

// ---------------- fused softmax + aggregate + bias (+relu), warp per dst node ----
#define LCACHE 128
template<int C, bool RELU>
__global__ void node_aggregate_kernel(const float* __restrict__ h,
                                      const float* __restrict__ bias,
                                      float* __restrict__ out) {
    __shared__ float lc[8][LCACHE];
    int warp = (blockIdx.x * blockDim.x + threadIdx.x) >> 5;
    int w    = (threadIdx.x >> 5);
    int lane = threadIdx.x & 31;
    if (warp >= N_NODES) return;
    int n   = warp;
    int beg = g_rowptr[n];
    int end = g_rowptr[n + 1];
    float ad = g_adst[n];

    float m = -CUDART_INF_F;
    for (int i = beg + lane; i < end; i += 32) {
        int s = g_csr_src[i];
        float l = g_asrc[s] + ad;
        l = (l > 0.0f) ? l : NEG_SLOPE * l;
        int off = i - beg;
        if (off < LCACHE) lc[w][off] = l;
        m = fmaxf(m, l);
    }
    #pragma unroll
    for (int o = 16; o > 0; o >>= 1)
        m = fmaxf(m, __shfl_xor_sync(0xffffffffu, m, o));
    __syncwarp();

    float den = 0.0f;
    float a0 = 0.f, a1 = 0.f, a2 = 0.f, a3 = 0.f;
    for (int i = beg; i < end; i++) {
        int off = i - beg;
        float l;
        if (off < LCACHE) {
            l = lc[w][off];
        } else {
            int s2 = g_csr_src[i];
            l = g_asrc[s2] + ad;
            l = (l > 0.0f) ? l : NEG_SLOPE * l;
        }
        float ev = __expf(l - m);
        den += ev;
        int s = g_csr_src[i];
        if (C == 128) {
            float4 v = ((const float4*)(h + (size_t)s * C))[lane];
            a0 += ev * v.x; a1 += ev * v.y; a2 += ev * v.z; a3 += ev * v.w;
        } else {
            float2 v = ((const float2*)(h + (size_t)s * C))[lane];
            a0 += ev * v.x; a1 += ev * v.y;
        }
    }

    float inv = 1.0f / (den + 1e-16f);
    if (C == 128) {
        float4 b = ((const float4*)bias)[lane];
        float4 r;
        r.x = a0 * inv + b.x; r.y = a1 * inv + b.y;
        r.z = a2 * inv + b.z; r.w = a3 * inv + b.w;
        if (RELU) {
            r.x = fmaxf(r.x, 0.f); r.y = fmaxf(r.y, 0.f);
            r.z = fmaxf(r.z, 0.f); r.w = fmaxf(r.w, 0.f);
        }
        ((float4*)(out + (size_t)n * C))[lane] = r;
    } else {
        float2 b = ((const float2*)bias)[lane];
        float2 r;
        r.x = a0 * inv + b.x; r.y = a1 * inv + b.y;
        if (RELU) { r.x = fmaxf(r.x, 0.f); r.y = fmaxf(r.y, 0.f); }
        ((float2*)(out + (size_t)n * C))[lane] = r;
    }
}

// ---------------- launch ----------------
extern "C" void kernel_launch(void* const* d_in, const int* in_sizes, int n_in,
                              void* d_out, int out_size) {
    const float* x   = (const float*)d_in[0];
    const int*   ei  = (const int*)d_in[1];
    const float* W1s = (const float*)d_in[2];
    const float* W1d = (const float*)d_in[3];
    const float* a1s = (const float*)d_in[4];
    const float* a1d = (const float*)d_in[5];
    const float* b1  = (const float*)d_in[6];
    const float* W2s = (const float*)d_in[7];
    const float* W2d = (const float*)d_in[8];
    const float* a2s = (const float*)d_in[9];
    const float* a2d = (const float*)d_in[10];
    const float* b2  = (const float*)d_in[11];
    float* out = (float*)d_out;

    const int* srcp = ei;
    const int* dstp = ei + N_EDGES;

    void *p_h1, *p_acc, *p_h2, *p_cnt;
    cudaGetSymbolAddress(&p_h1, g_h1);
    cudaGetSymbolAddress(&p_acc, g_acc);
    cudaGetSymbolAddress(&p_h2, g_h2);
    cudaGetSymbolAddress(&p_cnt, g_cnt);
    float* h1  = (float*)p_h1;
    float* acc = (float*)p_acc;
    float* h2  = (float*)p_h2;

    const int TB = 256;
    const int edgeBlocks     = (N_EDGES + TB - 1) / TB;
    const int nodeBlocks     = (N_NODES + TB - 1) / TB;
    const int nodeWarpBlocks = (N_NODES * 32 + TB - 1) / TB;
    const int gemmBlocks     = (N_NODES + 127) / 128;

    // ---------- CSR build (shared by both layers) ----------
    cudaMemsetAsync(p_cnt, 0, N_NODES * sizeof(int));
    hist_kernel<<<edgeBlocks, TB>>>(dstp);
    scan1_kernel<<<N_SCAN_BLOCKS, SCAN_BLK>>>();
    scan2_kernel<<<1, 128>>>();
    scan3_kernel<<<nodeBlocks, TB>>>();
    scatter_kernel<<<edgeBlocks, TB>>>(srcp, dstp);

    // ---------------- layer 1 ----------------
    compute_p_kernel<<<1, 128>>>(W1s, a1s, W1d, a1d, DIM_HID);
    node_av_kernel<<<nodeWarpBlocks, TB>>>(x);
    gemm_tf32_kernel<DIM_HID><<<gemmBlocks, 256>>>(x, W1s, h1, N_NODES);
    node_aggregate_kernel<DIM_HID, true><<<nodeWarpBlocks, TB>>>(h1, b1, acc);

    // ---------------- layer 2 ----------------
    compute_p_kernel<<<1, 128>>>(W2s, a2s, W2d, a2d, DIM_OUT);
    node_av_kernel<<<nodeWarpBlocks, TB>>>(acc);
    gemm_tf32_kernel<DIM_OUT><<<gemmBlocks, 256>>>(acc, W2s, h2, N_NODES);
    node_aggregate_kernel<DIM_OUT, false><<<nodeWarpBlocks, TB>>>(h2, b2, out);

    (void)in_sizes; (void)n_in; (void)out_size;
}

// round 5
// speedup vs baseline: 1.2134x; 1.2134x over previous
#include <cuda_runtime.h>
#include <cuda_fp16.h>
#include <cuda_bf16.h>
#include <math_constants.h>

// ---------------- problem constants ----------------
#define N_NODES 100000
#define N_EDGES 1600000
#define DIM_IN  128
#define DIM_HID 128
#define DIM_OUT 64
#define NEG_SLOPE 0.2f

#define KDIM 128                      // input dim of both GEMMs
#define NKS  (KDIM / 16)              // 8 k-steps of 16
#define PAD_TILES 6256                // ceil-pad of 16-row tiles (covers 782*8 and 391*16)

#define SCAN_BLK 1024
#define N_SCAN_BLOCKS ((N_NODES + SCAN_BLK - 1) / SCAN_BLK)   // 98

// ---------------- scratch (device globals; no allocation allowed) ----------
__device__ float  g_acc[(size_t)N_NODES * DIM_HID];           // layer1 output (fp32)
__device__ __half g_h1[(size_t)N_NODES * DIM_HID];            // x@W1s (fp16, gather-only)
__device__ __half g_h2[(size_t)N_NODES * DIM_OUT];            // acc@W2s (fp16, gather-only)
__device__ float  g_asrc[N_NODES];
__device__ float  g_adst[N_NODES];
__device__ float  g_p[2 * 128];

// fragment buffers (bf16x2 packed in uint32)
__device__ unsigned g_AfH[(size_t)PAD_TILES * NKS * 32 * 4];  // 25.6MB
__device__ unsigned g_AfL[(size_t)PAD_TILES * NKS * 32 * 4];  // 25.6MB
__device__ unsigned g_WfH[16 * NKS * 32 * 2];                 // up to COUT=128
__device__ unsigned g_WfL[16 * NKS * 32 * 2];

// CSR scratch
__device__ int g_cnt[N_NODES];
__device__ int g_incl[N_NODES];
__device__ int g_bsum[N_SCAN_BLOCKS];
__device__ int g_boff[N_SCAN_BLOCKS];
__device__ int g_rowptr[N_NODES + 1];
__device__ int g_woff[N_NODES];
__device__ int g_csr_src[N_EDGES];

// ---------------- CSR build ----------------
__global__ void hist_kernel(const int* __restrict__ dst) {
    int e = blockIdx.x * blockDim.x + threadIdx.x;
    if (e >= N_EDGES) return;
    int d = dst[e];
    if ((unsigned)d < N_NODES) atomicAdd(&g_cnt[d], 1);
}

__global__ void scan1_kernel() {
    __shared__ int s[SCAN_BLK];
    int tid = threadIdx.x;
    int i = blockIdx.x * SCAN_BLK + tid;
    s[tid] = (i < N_NODES) ? g_cnt[i] : 0;
    __syncthreads();
    #pragma unroll
    for (int off = 1; off < SCAN_BLK; off <<= 1) {
        int v = (tid >= off) ? s[tid - off] : 0;
        __syncthreads();
        s[tid] += v;
        __syncthreads();
    }
    if (i < N_NODES) g_incl[i] = s[tid];
    if (tid == SCAN_BLK - 1) g_bsum[blockIdx.x] = s[tid];
}

__global__ void scan2_kernel() {
    __shared__ int s[128];
    int tid = threadIdx.x;
    int v0 = (tid < N_SCAN_BLOCKS) ? g_bsum[tid] : 0;
    s[tid] = v0;
    __syncthreads();
    #pragma unroll
    for (int off = 1; off < 128; off <<= 1) {
        int v = (tid >= off) ? s[tid - off] : 0;
        __syncthreads();
        s[tid] += v;
        __syncthreads();
    }
    if (tid < N_SCAN_BLOCKS) g_boff[tid] = s[tid] - v0;
}

__global__ void scan3_kernel() {
    int i = blockIdx.x * blockDim.x + threadIdx.x;
    if (i >= N_NODES) return;
    int excl = g_incl[i] - g_cnt[i] + g_boff[i / SCAN_BLK];
    g_rowptr[i] = excl;
    g_woff[i]   = excl;
    if (i == 0) g_rowptr[N_NODES] = N_EDGES;
}

__global__ void scatter_kernel(const int* __restrict__ src, const int* __restrict__ dst) {
    int e = blockIdx.x * blockDim.x + threadIdx.x;
    if (e >= N_EDGES) return;
    int s = src[e];
    int d = dst[e];
    if ((unsigned)s >= N_NODES || (unsigned)d >= N_NODES) return;
    int pos = atomicAdd(&g_woff[d], 1);
    g_csr_src[pos] = s;
}

// ---------------- per-layer node prep ----------------
__global__ void compute_p_kernel(const float* __restrict__ Ws, const float* __restrict__ as_,
                                 const float* __restrict__ Wd, const float* __restrict__ ad_,
                                 int C) {
    int i = threadIdx.x;  // 0..127
    float s = 0.f, d = 0.f;
    for (int c = 0; c < C; c++) {
        s += Ws[i * C + c] * as_[c];
        d += Wd[i * C + c] * ad_[c];
    }
    g_p[i] = s;
    g_p[128 + i] = d;
}

__global__ void node_av_kernel(const float* __restrict__ feat) {
    int warp = (blockIdx.x * blockDim.x + threadIdx.x) >> 5;
    int lane = threadIdx.x & 31;
    if (warp >= N_NODES) return;
    const float* f = feat + (size_t)warp * 128;
    float4 v = ((const float4*)f)[lane];
    float4 ps = ((const float4*)g_p)[lane];
    float4 pd = ((const float4*)(g_p + 128))[lane];
    float s = v.x * ps.x + v.y * ps.y + v.z * ps.z + v.w * ps.w;
    float d = v.x * pd.x + v.y * pd.y + v.z * pd.z + v.w * pd.w;
    #pragma unroll
    for (int o = 16; o > 0; o >>= 1) {
        s += __shfl_down_sync(0xffffffffu, s, o);
        d += __shfl_down_sync(0xffffffffu, d, o);
    }
    if (lane == 0) {
        g_asrc[warp] = s;
        g_adst[warp] = d;
    }
}

// ---------------- bf16 hi/lo split helpers ----------------
__device__ __forceinline__ void split_bf16(float x, __nv_bfloat16& h, __nv_bfloat16& l) {
    h = __float2bfloat16_rn(x);
    l = __float2bfloat16_rn(x - __bfloat162float(h));
}
__device__ __forceinline__ unsigned pack_bf16(__nv_bfloat16 a, __nv_bfloat16 b) {
    __nv_bfloat162 t;
    t.x = a; t.y = b;            // low half = first element
    return *(unsigned*)&t;
}

// ---------------- A-operand conversion: X[nrows,128] -> fragment-major hi/lo ----
// tile = blockIdx.x (16 rows), ks = warp-in-block (0..7)
__global__ void convertA_kernel(const float* __restrict__ X, int nrows) {
    int tile = blockIdx.x;
    int ks   = threadIdx.x >> 5;
    int lane = threadIdx.x & 31;
    int g = lane >> 2, t = lane & 3;
    size_t base = (((size_t)tile * NKS + ks) * 32 + lane) * 4;
    #pragma unroll
    for (int r = 0; r < 4; r++) {
        int row = tile * 16 + g + (r & 1) * 8;
        int col = ks * 16 + 2 * t + (r >> 1) * 8;
        float2 v = make_float2(0.f, 0.f);
        if (row < nrows) v = *(const float2*)&X[(size_t)row * KDIM + col];
        __nv_bfloat16 h0, l0, h1, l1;
        split_bf16(v.x, h0, l0);
        split_bf16(v.y, h1, l1);
        g_AfH[base + r] = pack_bf16(h0, h1);
        g_AfL[base + r] = pack_bf16(l0, l1);
    }
}

// ---------------- B-operand conversion: W[128,COUT] -> fragment-major hi/lo ----
// ct = blockIdx.x (8 cols), ks = warp-in-block (0..7)
__global__ void convertW_kernel(const float* __restrict__ W, int COUT) {
    int ct   = blockIdx.x;
    int ks   = threadIdx.x >> 5;
    int lane = threadIdx.x & 31;
    int g = lane >> 2, t = lane & 3;
    size_t base = (((size_t)ct * NKS + ks) * 32 + lane) * 2;
    #pragma unroll
    for (int r = 0; r < 2; r++) {
        int k   = ks * 16 + 2 * t + r * 8;
        int col = ct * 8 + g;
        float e0 = W[(size_t)k * COUT + col];
        float e1 = W[(size_t)(k + 1) * COUT + col];
        __nv_bfloat16 h0, l0, h1, l1;
        split_bf16(e0, h0, l0);
        split_bf16(e1, h1, l1);
        g_WfH[base + r] = pack_bf16(h0, h1);
        g_WfL[base + r] = pack_bf16(l0, l1);
    }
}

// ---------------- bf16 3x mma GEMM (no smem, no sync) ----------------
__device__ __forceinline__ void mma_bf16(float c[4], const unsigned a[4], const unsigned b[2]) {
    asm volatile(
        "mma.sync.aligned.m16n8k16.row.col.f32.bf16.bf16.f32 "
        "{%0,%1,%2,%3}, {%4,%5,%6,%7}, {%8,%9}, {%0,%1,%2,%3};"
        : "+f"(c[0]), "+f"(c[1]), "+f"(c[2]), "+f"(c[3])
        : "r"(a[0]), "r"(a[1]), "r"(a[2]), "r"(a[3]), "r"(b[0]), "r"(b[1]));
}

// H[nrows, COUT] (fp16) = frag(X) @ frag(W); COUT in {128, 64}
template<int COUT>
__global__ __launch_bounds__(256, 2)
void gemm_frag_kernel(__half* __restrict__ H, int nrows) {
    constexpr int WN = (COUT == 128) ? 2 : 1;     // warps along n
    constexpr int WMCNT = 8 / WN;                 // warps along m
    constexpr int ROWS = WMCNT * 32;              // rows per block (128 or 256)

    int wid  = threadIdx.x >> 5;
    int lane = threadIdx.x & 31;
    int g = lane >> 2, t = lane & 3;
    int warp_m = (COUT == 128) ? (wid >> 1) : wid;
    int warp_n = (COUT == 128) ? (wid & 1) : 0;
    int base_tile = blockIdx.x * (ROWS / 16) + warp_m * 2;

    const uint4* AfH = (const uint4*)g_AfH;
    const uint4* AfL = (const uint4*)g_AfL;
    const uint2* WfH = (const uint2*)g_WfH;
    const uint2* WfL = (const uint2*)g_WfL;

    float c[2][8][4];
    #pragma unroll
    for (int mt = 0; mt < 2; mt++)
        #pragma unroll
        for (int nt = 0; nt < 8; nt++)
            #pragma unroll
            for (int i = 0; i < 4; i++) c[mt][nt][i] = 0.0f;

    #pragma unroll
    for (int ks = 0; ks < NKS; ks++) {
        uint4 Ah[2], Al[2];
        #pragma unroll
        for (int mt = 0; mt < 2; mt++) {
            size_t ai = ((size_t)(base_tile + mt) * NKS + ks) * 32 + lane;
            Ah[mt] = AfH[ai];
            Al[mt] = AfL[ai];
        }
        #pragma unroll
        for (int nt = 0; nt < 8; nt++) {
            int ct = warp_n * 8 + nt;
            size_t bi = ((size_t)ct * NKS + ks) * 32 + lane;
            uint2 Bh = WfH[bi];
            uint2 Bl = WfL[bi];
            #pragma unroll
            for (int mt = 0; mt < 2; mt++) {
                mma_bf16(c[mt][nt], (const unsigned*)&Ah[mt], (const unsigned*)&Bh);
                mma_bf16(c[mt][nt], (const unsigned*)&Ah[mt], (const unsigned*)&Bl);
                mma_bf16(c[mt][nt], (const unsigned*)&Al[mt], (const unsigned*)&Bh);
            }
        }
    }

    // epilogue: fp16 output
    #pragma unroll
    for (int mt = 0; mt < 2; mt++) {
        int r0 = blockIdx.x * ROWS + warp_m * 32 + mt * 16 + g;
        #pragma unroll
        for (int nt = 0; nt < 8; nt++) {
            int col = (warp_n * 8 + nt) * 8 + 2 * t;
            if (r0 < nrows)
                *(__half2*)&H[(size_t)r0 * COUT + col] =
                    __floats2half2_rn(c[mt][nt][0], c[mt][nt][1]);
            if (r0 + 8 < nrows)
                *(__half2*)&H[(size_t)(r0 + 8) * COUT + col] =
                    __floats2half2_rn(c[mt][nt][2], c[mt][nt][3]);
        }
    }
}

// ---------------- fused softmax + aggregate + bias (+relu), warp per dst node ----
#define LCACHE 128
template<int C, bool RELU>
__global__ void node_aggregate_kernel(const __half* __restrict__ h,
                                      const float* __restrict__ bias,
                                      float* __restrict__ out) {
    __shared__ float lc[8][LCACHE];
    int warp = (blockIdx.x * blockDim.x + threadIdx.x) >> 5;
    int w    = (threadIdx.x >> 5);
    int lane = threadIdx.x & 31;
    if (warp >= N_NODES) return;
    int n   = warp;
    int beg = g_rowptr[n];
    int end = g_rowptr[n + 1];
    float ad = g_adst[n];

    float m = -CUDART_INF_F;
    for (int i = beg + lane; i < end; i += 32) {
        int s = g_csr_src[i];
        float l = g_asrc[s] + ad;
        l = (l > 0.0f) ? l : NEG_SLOPE * l;
        int off = i - beg;
        if (off < LCACHE) lc[w][off] = l;
        m = fmaxf(m, l);
    }
    #pragma unroll
    for (int o = 16; o > 0; o >>= 1)
        m = fmaxf(m, __shfl_xor_sync(0xffffffffu, m, o));
    __syncwarp();

    float den = 0.0f;
    float a0 = 0.f, a1 = 0.f, a2 = 0.f, a3 = 0.f;
    for (int i = beg; i < end; i++) {
        int off = i - beg;
        float l;
        if (off < LCACHE) {
            l = lc[w][off];
        } else {
            int s2 = g_csr_src[i];
            l = g_asrc[s2] + ad;
            l = (l > 0.0f) ? l : NEG_SLOPE * l;
        }
        float ev = __expf(l - m);
        den += ev;
        int s = g_csr_src[i];
        const __half* hp = h + (size_t)s * C;
        if (C == 128) {
            uint2 raw = ((const uint2*)hp)[lane];          // 4 halves: cols 4l..4l+3
            float2 f01 = __half22float2(*(const __half2*)&raw.x);
            float2 f23 = __half22float2(*(const __half2*)&raw.y);
            a0 += ev * f01.x; a1 += ev * f01.y;
            a2 += ev * f23.x; a3 += ev * f23.y;
        } else {
            __half2 raw = ((const __half2*)hp)[lane];      // 2 halves: cols 2l..2l+1
            float2 f = __half22float2(raw);
            a0 += ev * f.x; a1 += ev * f.y;
        }
    }

    float inv = 1.0f / (den + 1e-16f);
    if (C == 128) {
        float4 b = ((const float4*)bias)[lane];
        float4 r;
        r.x = a0 * inv + b.x; r.y = a1 * inv + b.y;
        r.z = a2 * inv + b.z; r.w = a3 * inv + b.w;
        if (RELU) {
            r.x = fmaxf(r.x, 0.f); r.y = fmaxf(r.y, 0.f);
            r.z = fmaxf(r.z, 0.f); r.w = fmaxf(r.w, 0.f);
        }
        ((float4*)(out + (size_t)n * C))[lane] = r;
    } else {
        float2 b = ((const float2*)bias)[lane];
        float2 r;
        r.x = a0 * inv + b.x; r.y = a1 * inv + b.y;
        if (RELU) { r.x = fmaxf(r.x, 0.f); r.y = fmaxf(r.y, 0.f); }
        ((float2*)(out + (size_t)n * C))[lane] = r;
    }
}

// ---------------- launch ----------------
extern "C" void kernel_launch(void* const* d_in, const int* in_sizes, int n_in,
                              void* d_out, int out_size) {
    const float* x   = (const float*)d_in[0];
    const int*   ei  = (const int*)d_in[1];
    const float* W1s = (const float*)d_in[2];
    const float* W1d = (const float*)d_in[3];
    const float* a1s = (const float*)d_in[4];
    const float* a1d = (const float*)d_in[5];
    const float* b1  = (const float*)d_in[6];
    const float* W2s = (const float*)d_in[7];
    const float* W2d = (const float*)d_in[8];
    const float* a2s = (const float*)d_in[9];
    const float* a2d = (const float*)d_in[10];
    const float* b2  = (const float*)d_in[11];
    float* out = (float*)d_out;

    const int* srcp = ei;
    const int* dstp = ei + N_EDGES;

    void *p_acc, *p_cnt, *p_h1, *p_h2;
    cudaGetSymbolAddress(&p_acc, g_acc);
    cudaGetSymbolAddress(&p_cnt, g_cnt);
    cudaGetSymbolAddress(&p_h1, g_h1);
    cudaGetSymbolAddress(&p_h2, g_h2);
    float*  acc = (float*)p_acc;
    __half* h1  = (__half*)p_h1;
    __half* h2  = (__half*)p_h2;

    const int TB = 256;
    const int edgeBlocks     = (N_EDGES + TB - 1) / TB;
    const int nodeBlocks     = (N_NODES + TB - 1) / TB;
    const int nodeWarpBlocks = (N_NODES * 32 + TB - 1) / TB;

    // ---------- CSR build (shared by both layers) ----------
    cudaMemsetAsync(p_cnt, 0, N_NODES * sizeof(int));
    hist_kernel<<<edgeBlocks, TB>>>(dstp);
    scan1_kernel<<<N_SCAN_BLOCKS, SCAN_BLK>>>();
    scan2_kernel<<<1, 128>>>();
    scan3_kernel<<<nodeBlocks, TB>>>();
    scatter_kernel<<<edgeBlocks, TB>>>(srcp, dstp);

    // ---------------- layer 1 ----------------
    compute_p_kernel<<<1, 128>>>(W1s, a1s, W1d, a1d, DIM_HID);
    node_av_kernel<<<nodeWarpBlocks, TB>>>(x);
    convertA_kernel<<<PAD_TILES, 256>>>(x, N_NODES);
    convertW_kernel<<<DIM_HID / 8, 256>>>(W1s, DIM_HID);
    gemm_frag_kernel<DIM_HID><<<(N_NODES + 127) / 128, 256>>>(h1, N_NODES);
    node_aggregate_kernel<DIM_HID, true><<<nodeWarpBlocks, TB>>>(h1, b1, acc);

    // ---------------- layer 2 ----------------
    compute_p_kernel<<<1, 128>>>(W2s, a2s, W2d, a2d, DIM_OUT);
    node_av_kernel<<<nodeWarpBlocks, TB>>>(acc);
    convertA_kernel<<<PAD_TILES, 256>>>(acc, N_NODES);
    convertW_kernel<<<DIM_OUT / 8, 256>>>(W2s, DIM_OUT);
    gemm_frag_kernel<DIM_OUT><<<(N_NODES + 255) / 256, 256>>>(h2, N_NODES);
    node_aggregate_kernel<DIM_OUT, false><<<nodeWarpBlocks, TB>>>(h2, b2, out);

    (void)in_sizes; (void)n_in; (void)out_size;
}

// round 6
// speedup vs baseline: 1.4847x; 1.2236x over previous
#include <cuda_runtime.h>
#include <cuda_fp16.h>
#include <cuda_bf16.h>
#include <math_constants.h>

// ---------------- problem constants ----------------
#define N_NODES 100000
#define N_EDGES 1600000
#define DIM_IN  128
#define DIM_HID 128
#define DIM_OUT 64
#define NEG_SLOPE 0.2f

#define KDIM 128
#define NKS  (KDIM / 16)              // 8 k-steps of 16
#define PAD_TILES 6256                // covers 782*8 (gemm1) and 391*16 (gemm2)

#define SCAN_BLK 1024
#define N_SCAN_BLOCKS ((N_NODES + SCAN_BLK - 1) / SCAN_BLK)   // 98

// ---------------- scratch (device globals; no allocation allowed) ----------
__device__ __half g_h1[(size_t)N_NODES * DIM_HID];            // x@W1s (fp16, gather-only)
__device__ __half g_h2[(size_t)N_NODES * DIM_OUT];            // h@W2s (fp16, gather-only)
__device__ float  g_asrc[N_NODES],  g_adst[N_NODES];          // layer1
__device__ float  g_asrc2[N_NODES], g_adst2[N_NODES];         // layer2
__device__ float  g_p1[2 * 128];
__device__ float  g_p2[2 * 128];

// fragment buffers (bf16x2 packed in uint32); zero-init at module load
__device__ unsigned g_AfH[(size_t)PAD_TILES * NKS * 32 * 4];
__device__ unsigned g_AfL[(size_t)PAD_TILES * NKS * 32 * 4];
__device__ unsigned g_WfH1[16 * NKS * 32 * 2], g_WfL1[16 * NKS * 32 * 2];
__device__ unsigned g_WfH2[8  * NKS * 32 * 2], g_WfL2[8  * NKS * 32 * 2];

// CSR scratch
__device__ int g_cnt[N_NODES];
__device__ int g_incl[N_NODES];
__device__ int g_bsum[N_SCAN_BLOCKS];
__device__ int g_boff[N_SCAN_BLOCKS];
__device__ int g_rowptr[N_NODES + 1];
__device__ int g_woff[N_NODES];
__device__ int g_csr_src[N_EDGES];

// ---------------- CSR build ----------------
__global__ void hist_kernel(const int* __restrict__ dst) {
    int e = blockIdx.x * blockDim.x + threadIdx.x;
    if (e >= N_EDGES) return;
    int d = dst[e];
    if ((unsigned)d < N_NODES) atomicAdd(&g_cnt[d], 1);
}

// block-wide inclusive scan via shfl warp scans (1024 threads)
__global__ void scan1_kernel() {
    __shared__ int wsum[32];
    int tid  = threadIdx.x;
    int lane = tid & 31;
    int wid  = tid >> 5;
    int i = blockIdx.x * SCAN_BLK + tid;
    int x = (i < N_NODES) ? g_cnt[i] : 0;
    #pragma unroll
    for (int off = 1; off < 32; off <<= 1) {
        int y = __shfl_up_sync(0xffffffffu, x, off);
        if (lane >= off) x += y;
    }
    if (lane == 31) wsum[wid] = x;
    __syncthreads();
    if (wid == 0) {
        int y = wsum[lane];
        #pragma unroll
        for (int off = 1; off < 32; off <<= 1) {
            int z = __shfl_up_sync(0xffffffffu, y, off);
            if (lane >= off) y += z;
        }
        wsum[lane] = y;
    }
    __syncthreads();
    if (wid > 0) x += wsum[wid - 1];
    if (i < N_NODES) g_incl[i] = x;
    if (tid == SCAN_BLK - 1) g_bsum[blockIdx.x] = x;
}

__global__ void scan2_kernel() {
    __shared__ int s[128];
    int tid = threadIdx.x;
    int v0 = (tid < N_SCAN_BLOCKS) ? g_bsum[tid] : 0;
    s[tid] = v0;
    __syncthreads();
    #pragma unroll
    for (int off = 1; off < 128; off <<= 1) {
        int v = (tid >= off) ? s[tid - off] : 0;
        __syncthreads();
        s[tid] += v;
        __syncthreads();
    }
    if (tid < N_SCAN_BLOCKS) g_boff[tid] = s[tid] - v0;
}

__global__ void scan3_kernel() {
    int i = blockIdx.x * blockDim.x + threadIdx.x;
    if (i >= N_NODES) return;
    int excl = g_incl[i] - g_cnt[i] + g_boff[i / SCAN_BLK];
    g_rowptr[i] = excl;
    g_woff[i]   = excl;
    if (i == 0) g_rowptr[N_NODES] = N_EDGES;
}

__global__ void scatter_kernel(const int* __restrict__ src, const int* __restrict__ dst) {
    int e = blockIdx.x * blockDim.x + threadIdx.x;
    if (e >= N_EDGES) return;
    int s = src[e];
    int d = dst[e];
    if ((unsigned)s >= N_NODES || (unsigned)d >= N_NODES) return;
    int pos = atomicAdd(&g_woff[d], 1);
    g_csr_src[pos] = s;
}

// ---------------- p-vector: p[i] = sum_c W[i,c]*att[c] ----------------
__global__ void compute_p_kernel(const float* __restrict__ Ws, const float* __restrict__ as_,
                                 const float* __restrict__ Wd, const float* __restrict__ ad_,
                                 int C, float* __restrict__ pout) {
    int i = threadIdx.x;  // 0..127
    float s = 0.f, d = 0.f;
    for (int c = 0; c < C; c++) {
        s += Ws[i * C + c] * as_[c];
        d += Wd[i * C + c] * ad_[c];
    }
    pout[i] = s;
    pout[128 + i] = d;
}

// ---------------- bf16 split / pack / frag-scatter helpers ----------------
__device__ __forceinline__ void split_bf16(float x, __nv_bfloat16& h, __nv_bfloat16& l) {
    h = __float2bfloat16_rn(x);
    l = __float2bfloat16_rn(x - __bfloat162float(h));
}
__device__ __forceinline__ unsigned pack_bf16(__nv_bfloat16 a, __nv_bfloat16 b) {
    __nv_bfloat162 t;
    t.x = a; t.y = b;
    return *(unsigned*)&t;
}

// Scatter one row (node n) into the A-fragment buffers. Lane holds cols 4l..4l+3.
__device__ __forceinline__ void write_frag_row(int n, int lane, float4 v) {
    int tile = n >> 4;
    int g    = n & 7;
    int r8   = (n >> 3) & 1;
    int ks   = lane >> 2;
    int j    = lane & 3;
    int t0   = ((4 * j) & 7) >> 1;        // 0,2,0,2
    int reg  = r8 + ((j & 2) ? 2 : 0);
    size_t blockbase = (size_t)(tile * 8 + ks) * 128;   // words per (tile,ks) block
    __nv_bfloat16 h0, l0, h1, l1, h2, l2, h3, l3;
    split_bf16(v.x, h0, l0); split_bf16(v.y, h1, l1);
    split_bf16(v.z, h2, l2); split_bf16(v.w, h3, l3);
    size_t w0 = blockbase + (size_t)(g * 4 + t0) * 4 + reg;
    size_t w1 = blockbase + (size_t)(g * 4 + t0 + 1) * 4 + reg;
    g_AfH[w0] = pack_bf16(h0, h1);
    g_AfL[w0] = pack_bf16(l0, l1);
    g_AfH[w1] = pack_bf16(h2, h3);
    g_AfL[w1] = pack_bf16(l2, l3);
}

// ---------------- row_prep: a_src/a_dst dots + A-fragments, one pass over x ----
__global__ void row_prep_kernel(const float* __restrict__ feat) {
    int warp = (blockIdx.x * blockDim.x + threadIdx.x) >> 5;
    int lane = threadIdx.x & 31;
    if (warp >= PAD_TILES * 16) return;
    if (warp >= N_NODES) {                 // zero padding tiles
        write_frag_row(warp, lane, make_float4(0.f, 0.f, 0.f, 0.f));
        return;
    }
    float4 v = ((const float4*)(feat + (size_t)warp * 128))[lane];
    float4 ps = ((const float4*)g_p1)[lane];
    float4 pd = ((const float4*)(g_p1 + 128))[lane];
    float s = v.x * ps.x + v.y * ps.y + v.z * ps.z + v.w * ps.w;
    float d = v.x * pd.x + v.y * pd.y + v.z * pd.z + v.w * pd.w;
    #pragma unroll
    for (int o = 16; o > 0; o >>= 1) {
        s += __shfl_xor_sync(0xffffffffu, s, o);
        d += __shfl_xor_sync(0xffffffffu, d, o);
    }
    if (lane == 0) {
        g_asrc[warp] = s;
        g_adst[warp] = d;
    }
    write_frag_row(warp, lane, v);
}

// ---------------- W conversion -> fragment-major hi/lo ----------------
__global__ void convertW_kernel(const float* __restrict__ W, int COUT,
                                unsigned* __restrict__ WfH, unsigned* __restrict__ WfL) {
    int ct   = blockIdx.x;
    int ks   = threadIdx.x >> 5;
    int lane = threadIdx.x & 31;
    int g = lane >> 2, t = lane & 3;
    size_t base = (((size_t)ct * NKS + ks) * 32 + lane) * 2;
    #pragma unroll
    for (int r = 0; r < 2; r++) {
        int k   = ks * 16 + 2 * t + r * 8;
        int col = ct * 8 + g;
        float e0 = W[(size_t)k * COUT + col];
        float e1 = W[(size_t)(k + 1) * COUT + col];
        __nv_bfloat16 h0, l0, h1, l1;
        split_bf16(e0, h0, l0);
        split_bf16(e1, h1, l1);
        WfH[base + r] = pack_bf16(h0, h1);
        WfL[base + r] = pack_bf16(l0, l1);
    }
}

// ---------------- bf16 3x mma GEMM (no smem, no sync) ----------------
__device__ __forceinline__ void mma_bf16(float c[4], const unsigned a[4], const unsigned b[2]) {
    asm volatile(
        "mma.sync.aligned.m16n8k16.row.col.f32.bf16.bf16.f32 "
        "{%0,%1,%2,%3}, {%4,%5,%6,%7}, {%8,%9}, {%0,%1,%2,%3};"
        : "+f"(c[0]), "+f"(c[1]), "+f"(c[2]), "+f"(c[3])
        : "r"(a[0]), "r"(a[1]), "r"(a[2]), "r"(a[3]), "r"(b[0]), "r"(b[1]));
}

template<int COUT>
__global__ __launch_bounds__(256, 2)
void gemm_frag_kernel(__half* __restrict__ H, int nrows,
                      const unsigned* __restrict__ WfHp, const unsigned* __restrict__ WfLp) {
    constexpr int WN = (COUT == 128) ? 2 : 1;
    constexpr int WMCNT = 8 / WN;
    constexpr int ROWS = WMCNT * 32;

    int wid  = threadIdx.x >> 5;
    int lane = threadIdx.x & 31;
    int g = lane >> 2, t = lane & 3;
    int warp_m = (COUT == 128) ? (wid >> 1) : wid;
    int warp_n = (COUT == 128) ? (wid & 1) : 0;
    int base_tile = blockIdx.x * (ROWS / 16) + warp_m * 2;

    const uint4* AfH = (const uint4*)g_AfH;
    const uint4* AfL = (const uint4*)g_AfL;
    const uint2* WfH = (const uint2*)WfHp;
    const uint2* WfL = (const uint2*)WfLp;

    float c[2][8][4];
    #pragma unroll
    for (int mt = 0; mt < 2; mt++)
        #pragma unroll
        for (int nt = 0; nt < 8; nt++)
            #pragma unroll
            for (int i = 0; i < 4; i++) c[mt][nt][i] = 0.0f;

    #pragma unroll
    for (int ks = 0; ks < NKS; ks++) {
        uint4 Ah[2], Al[2];
        #pragma unroll
        for (int mt = 0; mt < 2; mt++) {
            size_t ai = ((size_t)(base_tile + mt) * NKS + ks) * 32 + lane;
            Ah[mt] = AfH[ai];
            Al[mt] = AfL[ai];
        }
        #pragma unroll
        for (int nt = 0; nt < 8; nt++) {
            int ct = warp_n * 8 + nt;
            size_t bi = ((size_t)ct * NKS + ks) * 32 + lane;
            uint2 Bh = WfH[bi];
            uint2 Bl = WfL[bi];
            #pragma unroll
            for (int mt = 0; mt < 2; mt++) {
                mma_bf16(c[mt][nt], (const unsigned*)&Ah[mt], (const unsigned*)&Bh);
                mma_bf16(c[mt][nt], (const unsigned*)&Ah[mt], (const unsigned*)&Bl);
                mma_bf16(c[mt][nt], (const unsigned*)&Al[mt], (const unsigned*)&Bh);
            }
        }
    }

    #pragma unroll
    for (int mt = 0; mt < 2; mt++) {
        int r0 = blockIdx.x * ROWS + warp_m * 32 + mt * 16 + g;
        #pragma unroll
        for (int nt = 0; nt < 8; nt++) {
            int col = (warp_n * 8 + nt) * 8 + 2 * t;
            if (r0 < nrows)
                *(__half2*)&H[(size_t)r0 * COUT + col] =
                    __floats2half2_rn(c[mt][nt][0], c[mt][nt][1]);
            if (r0 + 8 < nrows)
                *(__half2*)&H[(size_t)(r0 + 8) * COUT + col] =
                    __floats2half2_rn(c[mt][nt][2], c[mt][nt][3]);
        }
    }
}

// ---------------- fused softmax + aggregate (+relu) [+ layer2 operand prep] ----
#define LCACHE 128
template<int C, bool RELU, bool FUSE2>
__global__ void node_aggregate_kernel(const __half* __restrict__ h,
                                      const float* __restrict__ bias,
                                      float* __restrict__ out,
                                      const float* __restrict__ asrc,
                                      const float* __restrict__ adst) {
    __shared__ float lc[8][LCACHE];
    int warp = (blockIdx.x * blockDim.x + threadIdx.x) >> 5;
    int w    = (threadIdx.x >> 5);
    int lane = threadIdx.x & 31;
    if (warp >= N_NODES) return;
    int n   = warp;
    int beg = g_rowptr[n];
    int end = g_rowptr[n + 1];
    float ad = adst[n];

    float m = -CUDART_INF_F;
    for (int i = beg + lane; i < end; i += 32) {
        int s = g_csr_src[i];
        float l = asrc[s] + ad;
        l = (l > 0.0f) ? l : NEG_SLOPE * l;
        int off = i - beg;
        if (off < LCACHE) lc[w][off] = l;
        m = fmaxf(m, l);
    }
    #pragma unroll
    for (int o = 16; o > 0; o >>= 1)
        m = fmaxf(m, __shfl_xor_sync(0xffffffffu, m, o));
    __syncwarp();

    float den = 0.0f;
    float a0 = 0.f, a1 = 0.f, a2 = 0.f, a3 = 0.f;
    for (int i = beg; i < end; i++) {
        int off = i - beg;
        float l;
        if (off < LCACHE) {
            l = lc[w][off];
        } else {
            int s2 = g_csr_src[i];
            l = asrc[s2] + ad;
            l = (l > 0.0f) ? l : NEG_SLOPE * l;
        }
        float ev = __expf(l - m);
        den += ev;
        int s = g_csr_src[i];
        const __half* hp = h + (size_t)s * C;
        if (C == 128) {
            uint2 raw = ((const uint2*)hp)[lane];
            float2 f01 = __half22float2(*(const __half2*)&raw.x);
            float2 f23 = __half22float2(*(const __half2*)&raw.y);
            a0 += ev * f01.x; a1 += ev * f01.y;
            a2 += ev * f23.x; a3 += ev * f23.y;
        } else {
            __half2 raw = ((const __half2*)hp)[lane];
            float2 f = __half22float2(raw);
            a0 += ev * f.x; a1 += ev * f.y;
        }
    }

    float inv = 1.0f / (den + 1e-16f);
    if (C == 128) {
        float4 b = ((const float4*)bias)[lane];
        float4 r;
        r.x = a0 * inv + b.x; r.y = a1 * inv + b.y;
        r.z = a2 * inv + b.z; r.w = a3 * inv + b.w;
        if (RELU) {
            r.x = fmaxf(r.x, 0.f); r.y = fmaxf(r.y, 0.f);
            r.z = fmaxf(r.z, 0.f); r.w = fmaxf(r.w, 0.f);
        }
        if (FUSE2) {
            // layer-2 attention dots + A-fragment scatter; g_acc never materialized
            float4 ps = ((const float4*)g_p2)[lane];
            float4 pd = ((const float4*)(g_p2 + 128))[lane];
            float s2 = r.x * ps.x + r.y * ps.y + r.z * ps.z + r.w * ps.w;
            float d2 = r.x * pd.x + r.y * pd.y + r.z * pd.z + r.w * pd.w;
            #pragma unroll
            for (int o = 16; o > 0; o >>= 1) {
                s2 += __shfl_xor_sync(0xffffffffu, s2, o);
                d2 += __shfl_xor_sync(0xffffffffu, d2, o);
            }
            if (lane == 0) {
                g_asrc2[n] = s2;
                g_adst2[n] = d2;
            }
            write_frag_row(n, lane, r);
        } else {
            ((float4*)(out + (size_t)n * C))[lane] = r;
        }
    } else {
        float2 b = ((const float2*)bias)[lane];
        float2 r;
        r.x = a0 * inv + b.x; r.y = a1 * inv + b.y;
        if (RELU) { r.x = fmaxf(r.x, 0.f); r.y = fmaxf(r.y, 0.f); }
        ((float2*)(out + (size_t)n * C))[lane] = r;
    }
}

// ---------------- launch ----------------
extern "C" void kernel_launch(void* const* d_in, const int* in_sizes, int n_in,
                              void* d_out, int out_size) {
    const float* x   = (const float*)d_in[0];
    const int*   ei  = (const int*)d_in[1];
    const float* W1s = (const float*)d_in[2];
    const float* W1d = (const float*)d_in[3];
    const float* a1s = (const float*)d_in[4];
    const float* a1d = (const float*)d_in[5];
    const float* b1  = (const float*)d_in[6];
    const float* W2s = (const float*)d_in[7];
    const float* W2d = (const float*)d_in[8];
    const float* a2s = (const float*)d_in[9];
    const float* a2d = (const float*)d_in[10];
    const float* b2  = (const float*)d_in[11];
    float* out = (float*)d_out;

    const int* srcp = ei;
    const int* dstp = ei + N_EDGES;

    void *p_cnt, *p_h1, *p_h2, *p_p1, *p_p2, *p_WfH1, *p_WfL1, *p_WfH2, *p_WfL2;
    void *p_asrc, *p_adst, *p_asrc2, *p_adst2;
    cudaGetSymbolAddress(&p_cnt, g_cnt);
    cudaGetSymbolAddress(&p_h1, g_h1);
    cudaGetSymbolAddress(&p_h2, g_h2);
    cudaGetSymbolAddress(&p_p1, g_p1);
    cudaGetSymbolAddress(&p_p2, g_p2);
    cudaGetSymbolAddress(&p_WfH1, g_WfH1);
    cudaGetSymbolAddress(&p_WfL1, g_WfL1);
    cudaGetSymbolAddress(&p_WfH2, g_WfH2);
    cudaGetSymbolAddress(&p_WfL2, g_WfL2);
    cudaGetSymbolAddress(&p_asrc, g_asrc);
    cudaGetSymbolAddress(&p_adst, g_adst);
    cudaGetSymbolAddress(&p_asrc2, g_asrc2);
    cudaGetSymbolAddress(&p_adst2, g_adst2);
    __half* h1 = (__half*)p_h1;
    __half* h2 = (__half*)p_h2;

    // one-time side stream + events (created on the eager correctness call)
    static cudaStream_t s_side = nullptr;
    static cudaEvent_t ev_fork = nullptr, ev_join = nullptr;
    if (!s_side) {
        cudaStreamCreateWithFlags(&s_side, cudaStreamNonBlocking);
        cudaEventCreateWithFlags(&ev_fork, cudaEventDisableTiming);
        cudaEventCreateWithFlags(&ev_join, cudaEventDisableTiming);
    }

    const int TB = 256;
    const int edgeBlocks = (N_EDGES + TB - 1) / TB;
    const int nodeBlocks = (N_NODES + TB - 1) / TB;
    const int nodeWarpBlocks = (N_NODES * 32 + TB - 1) / TB;
    const int prepBlocks = (PAD_TILES * 16 * 32) / TB;        // 12512

    // ---- fork: CSR build on side stream (independent of GEMM chain) ----
    cudaEventRecord(ev_fork, 0);
    cudaStreamWaitEvent(s_side, ev_fork, 0);
    cudaMemsetAsync(p_cnt, 0, N_NODES * sizeof(int), s_side);
    hist_kernel<<<edgeBlocks, TB, 0, s_side>>>(dstp);
    scan1_kernel<<<N_SCAN_BLOCKS, SCAN_BLK, 0, s_side>>>();
    scan2_kernel<<<1, 128, 0, s_side>>>();
    scan3_kernel<<<nodeBlocks, TB, 0, s_side>>>();
    scatter_kernel<<<edgeBlocks, TB, 0, s_side>>>(srcp, dstp);
    cudaEventRecord(ev_join, s_side);

    // ---- main chain on default stream ----
    compute_p_kernel<<<1, 128>>>(W1s, a1s, W1d, a1d, DIM_HID, (float*)p_p1);
    compute_p_kernel<<<1, 128>>>(W2s, a2s, W2d, a2d, DIM_OUT, (float*)p_p2);
    convertW_kernel<<<DIM_HID / 8, 256>>>(W1s, DIM_HID, (unsigned*)p_WfH1, (unsigned*)p_WfL1);
    convertW_kernel<<<DIM_OUT / 8, 256>>>(W2s, DIM_OUT, (unsigned*)p_WfH2, (unsigned*)p_WfL2);
    row_prep_kernel<<<prepBlocks, TB>>>(x);
    gemm_frag_kernel<DIM_HID><<<(N_NODES + 127) / 128, 256>>>(h1, N_NODES,
                                                              (unsigned*)p_WfH1, (unsigned*)p_WfL1);

    // ---- join: aggregate needs CSR + gemm1 ----
    cudaStreamWaitEvent(0, ev_join, 0);
    node_aggregate_kernel<DIM_HID, true, true><<<nodeWarpBlocks, TB>>>(
        h1, b1, nullptr, (const float*)p_asrc, (const float*)p_adst);
    gemm_frag_kernel<DIM_OUT><<<(N_NODES + 255) / 256, 256>>>(h2, N_NODES,
                                                              (unsigned*)p_WfH2, (unsigned*)p_WfL2);
    node_aggregate_kernel<DIM_OUT, false, false><<<nodeWarpBlocks, TB>>>(
        h2, b2, out, (const float*)p_asrc2, (const float*)p_adst2);

    (void)in_sizes; (void)n_in; (void)out_size;
}